// round 1
// baseline (speedup 1.0000x reference)
#include <cuda_runtime.h>
#include <cstddef>

// Problem constants (fixed by the dataset)
#define Bq 256
#define Sq 4096
#define Hq 64
#define Cq 32            // chunks along S
#define Lq (Sq / Cq)     // 128 elements per chunk

// Scratch: per-(b,chunk,h) partial sums, then exclusive prefixes (carries).
// 256*32*64 floats = 2 MB.
__device__ float g_part[(size_t)Bq * Cq * Hq];

// wrap(p) = atan2(sin p, cos p) = p - 2*pi*rint(p/(2*pi)), split-constant for accuracy.
__device__ __forceinline__ float step_acc(float xv, float we, float be, float om, float acc) {
    const float INV_2PI     = 0.15915494309189535f;
    const float TWO_PI_HI   = 6.2831855f;       // fp32 nearest to 2*pi
    const float TWO_PI_NLO  = 1.7484556e-7f;    // -(2*pi - TWO_PI_HI)
    float p = fmaf(xv, we, be);
    float k = rintf(p * INV_2PI);
    float d = fmaf(-k, TWO_PI_HI, p);
    d = fmaf(k, TWO_PI_NLO, d);
    return fmaf(om, d, acc);                    // acc += omega * delta
}

// ---------------- Phase 1: per-chunk sums of omega*delta ----------------
__global__ void __launch_bounds__(Hq) k_partials(const float* __restrict__ x,
                                                 const float* __restrict__ W_e,
                                                 const float* __restrict__ b_e,
                                                 const float* __restrict__ omega) {
    int bc = blockIdx.x;            // b*Cq + c
    int h  = threadIdx.x;
    int b  = bc / Cq;
    int c  = bc % Cq;
    float we = W_e[h];
    float be = b_e[h];
    float om = omega[h];
    const float4* xp = (const float4*)(x + (size_t)b * Sq + (size_t)c * Lq);
    float acc = 0.0f;
#pragma unroll 4
    for (int i = 0; i < Lq / 4; ++i) {
        float4 v = __ldg(xp + i);
        acc = step_acc(v.x, we, be, om, acc);
        acc = step_acc(v.y, we, be, om, acc);
        acc = step_acc(v.z, we, be, om, acc);
        acc = step_acc(v.w, we, be, om, acc);
    }
    g_part[(size_t)bc * Hq + h] = acc;
}

// ---------------- Phase 2: exclusive prefix of chunk sums (per b,h) ----------------
__global__ void k_prefix() {
    int t = blockIdx.x * blockDim.x + threadIdx.x;  // t = b*Hq + h
    int b = t / Hq;
    int h = t % Hq;
    float run = 0.0f;
#pragma unroll
    for (int c = 0; c < Cq; ++c) {
        size_t idx = ((size_t)b * Cq + c) * Hq + h;
        float v = g_part[idx];
        g_part[idx] = run;
        run += v;
    }
}

// ---------------- Phase 3: recompute deltas, scan with carry, write Hseq ----------------
__global__ void __launch_bounds__(Hq) k_scan(const float* __restrict__ x,
                                             const float* __restrict__ W_e,
                                             const float* __restrict__ b_e,
                                             const float* __restrict__ omega,
                                             float* __restrict__ hseq) {
    int bc = blockIdx.x;            // b*Cq + c
    int h  = threadIdx.x;
    int b  = bc / Cq;
    int c  = bc % Cq;
    float we = W_e[h];
    float be = b_e[h];
    float om = omega[h];
    float acc = g_part[(size_t)bc * Hq + h];    // carry-in
    const float4* xp = (const float4*)(x + (size_t)b * Sq + (size_t)c * Lq);
    float* hp = hseq + ((size_t)b * Sq + (size_t)c * Lq) * Hq + h;
#pragma unroll 2
    for (int i = 0; i < Lq / 4; ++i) {
        float4 v = __ldg(xp + i);
        acc = step_acc(v.x, we, be, om, acc); hp[(size_t)(4 * i + 0) * Hq] = acc;
        acc = step_acc(v.y, we, be, om, acc); hp[(size_t)(4 * i + 1) * Hq] = acc;
        acc = step_acc(v.z, we, be, om, acc); hp[(size_t)(4 * i + 2) * Hq] = acc;
        acc = step_acc(v.w, we, be, om, acc); hp[(size_t)(4 * i + 3) * Hq] = acc;
    }
}

// ---------------- Phase 4: out[b] = [cos(ph), sin(ph), ph] . W_r + b_r ----------------
__global__ void __launch_bounds__(Hq) k_out(const float* __restrict__ hseq,
                                            const float* __restrict__ W_r,
                                            const float* __restrict__ b_r,
                                            float* __restrict__ out) {
    int b = blockIdx.x;
    int h = threadIdx.x;
    float ph = hseq[((size_t)b * Sq + (Sq - 1)) * Hq + h];
    float t = ph * W_r[2 * Hq + h];
    t = fmaf(cosf(ph), W_r[h], t);
    t = fmaf(sinf(ph), W_r[Hq + h], t);
    // 64-thread reduction: warp shuffle + 2-warp combine
#pragma unroll
    for (int o = 16; o > 0; o >>= 1)
        t += __shfl_down_sync(0xffffffffu, t, o);
    __shared__ float sh[2];
    if ((h & 31) == 0) sh[h >> 5] = t;
    __syncthreads();
    if (h == 0) out[b] = sh[0] + sh[1] + b_r[0];
}

extern "C" void kernel_launch(void* const* d_in, const int* in_sizes, int n_in,
                              void* d_out, int out_size) {
    const float* x     = (const float*)d_in[0];
    const float* W_e   = (const float*)d_in[1];
    const float* b_e   = (const float*)d_in[2];
    const float* omega = (const float*)d_in[3];
    const float* W_r   = (const float*)d_in[4];
    const float* b_r   = (const float*)d_in[5];

    // Output tuple (out, Hseq) flattened in order: out = B floats, then Hseq = B*S*H floats.
    float* out  = (float*)d_out;
    float* hseq = (float*)d_out + Bq;

    k_partials<<<Bq * Cq, Hq>>>(x, W_e, b_e, omega);
    k_prefix<<<(Bq * Hq) / 256, 256>>>();
    k_scan<<<Bq * Cq, Hq>>>(x, W_e, b_e, omega, hseq);
    k_out<<<Bq, Hq>>>(hseq, W_r, b_r, out);
}